// round 16
// baseline (speedup 1.0000x reference)
#include <cuda_runtime.h>
#include <stdint.h>
#include <math.h>

#define BATCH   4096
#define LEN     4096
#define NUM_SEG 4
#define SEG_LEN 1024
#define NV      3073        // LEN - SEG_LEN + 1
#define PADN    5120        // LEN + 2*512
#define NT1     320         // 5120 / 16
#define NT2     20          // 320 / 16
#define NBIN    2048
#define MCAP    48

// tanh pattern tables (precomputed once)
__device__ float g_pat[2][SEG_LEN];

__global__ void k_init(const float* __restrict__ pi, const float* __restrict__ pq) {
    int t = blockIdx.x * blockDim.x + threadIdx.x;
    if (t < SEG_LEN) {
        g_pat[0][t] = tanhf(pi[t]);
        g_pat[1][t] = tanhf(pq[t]);
    }
}

__global__ void __launch_bounds__(512, 4)
k_main(const float* __restrict__ x,
       const float* __restrict__ seg_scale,
       const int*   __restrict__ rand_cols,
       const int*   __restrict__ shifts_raw,
       float*       __restrict__ out) {
    __shared__ __align__(16) float BUF[PADN];   // power -> inner1 -> C
    __shared__ unsigned int US[NV];             // valid[l] bit patterns
    __shared__ unsigned int H[NBIN];            // coarse histogram
    __shared__ unsigned int HS[NUM_SEG][256];   // sub-histograms
    __shared__ unsigned int P1[512];            // decide partials
    __shared__ unsigned int P2[32];
    __shared__ unsigned long long klist[NUM_SEG][MCAP];
    __shared__ float        sA[NT1];
    __shared__ float        sB[32];
    __shared__ float        sExcl3;
    __shared__ int          mcnt[NUM_SEG];
    __shared__ int          sel_bin[NUM_SEG];   // absolute coarse bin, then combined
    __shared__ int          sel_rank[NUM_SEG];
    __shared__ unsigned int s_umin, s_umax, s_ovf;
    __shared__ int          s_start[NUM_SEG];
    __shared__ float        s_coef[NUM_SEG];
    __shared__ float        s_amp;

    const int b   = blockIdx.x;
    const int tid = threadIdx.x;
    const float* xr = x + (size_t)b * 2 * LEN;
    const float inv = 0.0009765625f;   // 1/1024, exact

    // ---------- phase 1: padded power (float4) + init ----------
    // power[j] = rn(rn(x0*x0) + rn(x1*x1)) — XLA reduce emitter, no contraction
    {
        const float4* x4 = (const float4*)xr;
        #pragma unroll
        for (int v = tid; v < 1024; v += 512) {
            float4 a = x4[v];
            float4 c = x4[1024 + v];
            float4 p;
            p.x = __fadd_rn(__fmul_rn(a.x, a.x), __fmul_rn(c.x, c.x));
            p.y = __fadd_rn(__fmul_rn(a.y, a.y), __fmul_rn(c.y, c.y));
            p.z = __fadd_rn(__fmul_rn(a.z, a.z), __fmul_rn(c.z, c.z));
            p.w = __fadd_rn(__fmul_rn(a.w, a.w), __fmul_rn(c.w, c.w));
            *(float4*)(BUF + 512 + 4 * v) = p;
        }
        BUF[tid] = 0.0f;           // pad [0,512)
        BUF[4608 + tid] = 0.0f;    // pad [4608,5120)
        H[tid] = 0u; H[512 + tid] = 0u; H[1024 + tid] = 0u; H[1536 + tid] = 0u;
        ((unsigned int*)HS)[tid] = 0u; ((unsigned int*)HS)[512 + tid] = 0u;
        if (tid < NUM_SEG) {
            sel_rank[tid] = rand_cols[b * NUM_SEG + tid];
            mcnt[tid]     = 0;
        }
        if (tid == 4) { s_umin = 0xFFFFFFFFu; s_umax = 0u; s_ovf = 0u; }
    }
    __syncthreads();

    // ---------- phase 2: XLA ReduceWindowRewriter blocked scan (base 16) ----------
    if (tid < NT1) {
        float4* t4 = (float4*)(BUF + 16 * tid);
        float4 v0 = t4[0], v1 = t4[1], v2 = t4[2], v3 = t4[3];
        float s;
        s = v0.x;
        s = __fadd_rn(s, v0.y); v0.y = s;
        s = __fadd_rn(s, v0.z); v0.z = s;
        s = __fadd_rn(s, v0.w); v0.w = s;
        s = __fadd_rn(s, v1.x); v1.x = s;
        s = __fadd_rn(s, v1.y); v1.y = s;
        s = __fadd_rn(s, v1.z); v1.z = s;
        s = __fadd_rn(s, v1.w); v1.w = s;
        s = __fadd_rn(s, v2.x); v2.x = s;
        s = __fadd_rn(s, v2.y); v2.y = s;
        s = __fadd_rn(s, v2.z); v2.z = s;
        s = __fadd_rn(s, v2.w); v2.w = s;
        s = __fadd_rn(s, v3.x); v3.x = s;
        s = __fadd_rn(s, v3.y); v3.y = s;
        s = __fadd_rn(s, v3.z); v3.z = s;
        s = __fadd_rn(s, v3.w); v3.w = s;
        t4[0] = v0; t4[1] = v1; t4[2] = v2; t4[3] = v3;
        sA[tid] = s;
    }
    __syncthreads();

    if (tid < NT2) {
        float acc = sA[16 * tid];
        #pragma unroll
        for (int r = 1; r < 16; r++) {
            acc = __fadd_rn(acc, sA[16 * tid + r]);
            sA[16 * tid + r] = acc;
        }
        sB[tid] = acc;
    }
    if (tid >= NT2 && tid < 32) sB[tid] = 0.0f;
    __syncthreads();

    if (tid < 2) {
        float acc = sB[16 * tid];
        #pragma unroll
        for (int r = 1; r < 16; r++) {
            acc = __fadd_rn(acc, sB[16 * tid + r]);
            sB[16 * tid + r] = acc;
        }
        if (tid == 0) sExcl3 = acc;
    }
    __syncthreads();

    if (tid < NT1) {
        int q = tid >> 4;
        float excl2;
        if (q == 0) excl2 = 0.0f;
        else {
            int j = q - 1;
            float e3 = (j < 16) ? 0.0f : sExcl3;
            excl2 = __fadd_rn(sB[j], e3);
        }
        sA[tid] = __fadd_rn(sA[tid], excl2);
    }
    __syncthreads();

    if (tid < NT1) {
        float excl1 = (tid == 0) ? 0.0f : sA[tid - 1];
        float4* t4 = (float4*)(BUF + 16 * tid);
        #pragma unroll
        for (int q = 0; q < 4; q++) {
            float4 v = t4[q];
            v.x = __fadd_rn(v.x, excl1);
            v.y = __fadd_rn(v.y, excl1);
            v.z = __fadd_rn(v.z, excl1);
            v.w = __fadd_rn(v.w, excl1);
            t4[q] = v;
        }
    }
    __syncthreads();
    const float* C = BUF;

    const int g  = tid >> 7;          // group 0..3; even = desc (high pool)
    const int lt = tid & 127;

    if (tid == 256) {
        float mean = __fadd_rn(__fdiv_rn(C[512 + LEN - 1], 8192.0f), 1e-12f);
        s_amp = 0.08f * sqrtf(mean);
    }

    // ---------- pass 1 (fused): fill US + coarse hist centered on u(0) ----------
    int sh1 = 13;
    unsigned int ubase;   // coarse base: bins are (u>>sh1) - ubase
    {
        unsigned int u0 = __float_as_uint(__fmul_rn(C[1023], inv));  // valid[0]
        ubase = (u0 >> 13) - 1024u;
        unsigned int ovf = 0u;
        for (int base = 0; base < NV; base += 512) {
            int l = base + tid;
            if (l < NV) {
                float c1 = C[l + 1023];
                float c0 = (l > 0) ? C[l - 1] : 0.0f;
                unsigned int u = __float_as_uint(__fmul_rn(__fsub_rn(c1, c0), inv));
                US[l] = u;
                unsigned int d = (u >> 13) - ubase;
                if (d < (unsigned)NBIN) atomicAdd(&H[d], 1u);
                else ovf = 1u;
            }
        }
        if (ovf) s_ovf = 1u;
    }
    __syncthreads();

    // fallback (CTA-uniform, ~never taken): exact min/max + dynamic shift rehist
    if (s_ovf) {
        unsigned int lmin = 0xFFFFFFFFu, lmax = 0u;
        for (int base = 0; base < NV; base += 512) {
            int l = base + tid;
            if (l < NV) {
                unsigned int u = US[l];
                lmin = min(lmin, u);
                lmax = max(lmax, u);
            }
        }
        lmin = __reduce_min_sync(0xFFFFFFFFu, lmin);
        lmax = __reduce_max_sync(0xFFFFFFFFu, lmax);
        if ((tid & 31) == 0) {
            atomicMin(&s_umin, lmin);
            atomicMax(&s_umax, lmax);
        }
        __syncthreads();
        unsigned int range = s_umax - s_umin;
        sh1 = max(13, 22 - __clz(range | 1u));
        ubase = s_umin >> sh1;
        H[tid] = 0u; H[512 + tid] = 0u; H[1024 + tid] = 0u; H[1536 + tid] = 0u;
        __syncthreads();
        for (int base = 0; base < NV; base += 512) {
            int l = base + tid;
            if (l < NV) atomicAdd(&H[(US[l] >> sh1) - ubase], 1u);
        }
        __syncthreads();
    }
    const int s2 = sh1 - 8;   // sub-band = 2^s2 ulp (32 ulp on fast path)

    // decide 1: coarse bin per group (partials + hierarchical walk)
    P1[tid] = H[4 * tid] + H[4 * tid + 1] + H[4 * tid + 2] + H[4 * tid + 3];
    __syncthreads();
    if (tid < 32) {
        unsigned int s = 0u;
        #pragma unroll
        for (int j = 0; j < 16; j++) s += P1[16 * tid + j];
        P2[tid] = s;
    }
    __syncthreads();
    if (lt == 0) {
        const bool desc = (g & 1) == 0;
        int r = sel_rank[g];
        unsigned int cum = 0;
        int bin;
        if (desc) {
            int t2 = 31;
            for (;; t2--) { if ((int)(cum + P2[t2]) > r) break; cum += P2[t2]; }
            int t1 = 16 * t2 + 15;
            for (;; t1--) { if ((int)(cum + P1[t1]) > r) break; cum += P1[t1]; }
            bin = 4 * t1 + 3;
            for (;; bin--) { if ((int)(cum + H[bin]) > r) break; cum += H[bin]; }
        } else {
            int t2 = 0;
            for (;; t2++) { if ((int)(cum + P2[t2]) > r) break; cum += P2[t2]; }
            int t1 = 16 * t2;
            for (;; t1++) { if ((int)(cum + P1[t1]) > r) break; cum += P1[t1]; }
            bin = 4 * t1;
            for (;; bin++) { if ((int)(cum + H[bin]) > r) break; cum += H[bin]; }
        }
        sel_bin[g]  = (int)(ubase + (unsigned int)bin);   // absolute coarse bin (u>>sh1)
        sel_rank[g] = r - (int)cum;
    }
    __syncthreads();

    // ---------- pass 2: sub-histogram (256 bins) inside each group's coarse bin ----------
    {
        const unsigned int a0 = (unsigned int)sel_bin[0], a1 = (unsigned int)sel_bin[1],
                           a2 = (unsigned int)sel_bin[2], a3 = (unsigned int)sel_bin[3];
        for (int base = 0; base < NV; base += 512) {
            int l = base + tid;
            if (l >= NV) continue;
            unsigned int u = US[l];
            unsigned int c = u >> sh1;
            unsigned int sb = (u >> s2) & 255u;
            if (c == a0) atomicAdd(&HS[0][sb], 1u);
            if (c == a1) atomicAdd(&HS[1][sb], 1u);
            if (c == a2) atomicAdd(&HS[2][sb], 1u);
            if (c == a3) atomicAdd(&HS[3][sb], 1u);
        }
    }
    __syncthreads();

    // decide 2: sub-bin per group (partials: 2 bins/thread, 128 per group)
    P1[(g << 7) | lt] = HS[g][2 * lt] + HS[g][2 * lt + 1];
    __syncthreads();
    if (lt == 0) {
        const bool desc = (g & 1) == 0;
        const unsigned int* part = P1 + (g << 7);
        int r = sel_rank[g];
        unsigned int cum = 0;
        int bin;
        if (desc) {
            int t1 = 127;
            for (;; t1--) { if ((int)(cum + part[t1]) > r) break; cum += part[t1]; }
            bin = 2 * t1 + 1;
            for (;; bin--) { if ((int)(cum + HS[g][bin]) > r) break; cum += HS[g][bin]; }
        } else {
            int t1 = 0;
            for (;; t1++) { if ((int)(cum + part[t1]) > r) break; cum += part[t1]; }
            bin = 2 * t1;
            for (;; bin++) { if ((int)(cum + HS[g][bin]) > r) break; cum += HS[g][bin]; }
        }
        sel_bin[g]  = (sel_bin[g] << 8) | bin;   // combined target: u>>s2
        sel_rank[g] = r - (int)cum;
    }
    __syncthreads();

    // ---------- pass 3: compact candidate keys per group ----------
    {
        const unsigned int t0 = (unsigned int)sel_bin[0], t1 = (unsigned int)sel_bin[1],
                           t2 = (unsigned int)sel_bin[2], t3 = (unsigned int)sel_bin[3];
        for (int base = 0; base < NV; base += 512) {
            int l = base + tid;
            if (l >= NV) continue;
            unsigned int u = US[l];
            unsigned int v = u >> s2;
            if (v == t0) { int p = atomicAdd(&mcnt[0], 1); if (p < MCAP) klist[0][p] = ((unsigned long long)(~u) << 32) | (unsigned int)l; }
            if (v == t1) { int p = atomicAdd(&mcnt[1], 1); if (p < MCAP) klist[1][p] = ((unsigned long long)( u) << 32) | (unsigned int)l; }
            if (v == t2) { int p = atomicAdd(&mcnt[2], 1); if (p < MCAP) klist[2][p] = ((unsigned long long)(~u) << 32) | (unsigned int)l; }
            if (v == t3) { int p = atomicAdd(&mcnt[3], 1); if (p < MCAP) klist[3][p] = ((unsigned long long)( u) << 32) | (unsigned int)l; }
        }
    }
    __syncthreads();

    // final: exact selection per group (one warp per group)
    if (lt < 32) {
        const bool desc = (g & 1) == 0;
        int n = mcnt[g];
        int idx = -1;
        if (n <= MCAP) {
            // warp-parallel rank count; keys distinct => unique rank-r match
            int r = min(sel_rank[g], n - 1);
            for (int j = lt; j < n; j += 32) {
                unsigned long long kj = klist[g][j];
                int rk = 0;
                for (int k = 0; k < n; k++) rk += (klist[g][k] < kj) ? 1 : 0;
                if (rk == r) idx = (int)(kj & 0xFFFFFFFFu);
            }
        } else {
            // guaranteed fallback (never in practice): warp-iterative min over US
            const unsigned int tg = (unsigned int)sel_bin[g];
            int r = sel_rank[g];
            unsigned long long cur = 0ULL;
            for (int it = 0; it <= r; it++) {
                unsigned long long mn = 0xFFFFFFFFFFFFFFFFULL;
                for (int l = lt; l < NV; l += 32) {
                    unsigned int u = US[l];
                    if ((u >> s2) == tg) {
                        unsigned int kh = desc ? ~u : u;
                        unsigned long long key = ((unsigned long long)kh << 32) | (unsigned int)l;
                        if (key > cur && key < mn) mn = key;
                    }
                }
                #pragma unroll
                for (int o = 16; o > 0; o >>= 1) {
                    unsigned long long other = __shfl_xor_sync(0xFFFFFFFFu, mn, o);
                    mn = min(mn, other);
                }
                cur = mn;
            }
            if (lt == 0) idx = (int)(cur & 0xFFFFFFFFu);
        }
        if (idx >= 0) {
            // starts: strict fp32 replication of reference op sequence
            const float a0f = 409.600006103515625f;   // fp32(0.1*4096)
            const float a3f = 3194.8798828125f;       // fp32(0.78*4096)
            float step   = __fdiv_rn(__fsub_rn(a3f, a0f), 3.0f);
            float anchor = __fadd_rn(a0f, __fmul_rn((float)g, step));
            float st = __fadd_rn(__fmul_rn(0.8f, anchor), __fmul_rn(0.2f, (float)idx));
            st = __fadd_rn(st, __fsub_rn((float)shifts_raw[b * NUM_SEG + g], 16.0f));
            float rr = rintf(st);                     // round-half-even == jnp.round
            rr = fminf(fmaxf(rr, 0.0f), 3072.0f);
            s_start[g] = (int)rr;
            s_coef[g]  = __fmul_rn(s_amp, fmaxf(seg_scale[g], 0.0f));
        }
    }
    __syncthreads();

    // ---------- apply (float4, per-chunk segment skip) ----------
    {
        const float4* x4 = (const float4*)xr;
        float4* o4 = (float4*)(out + (size_t)b * 2 * LEN);
        const int   st0 = s_start[0], st1 = s_start[1], st2 = s_start[2], st3 = s_start[3];
        const float cf0 = s_coef[0],  cf1 = s_coef[1],  cf2 = s_coef[2],  cf3 = s_coef[3];

        #pragma unroll
        for (int v = tid; v < 1024; v += 512) {
            int l = 4 * v;
            float4 xa = x4[v];
            float4 xb = x4[1024 + v];
            float a[4] = {0.f, 0.f, 0.f, 0.f};
            float c[4] = {0.f, 0.f, 0.f, 0.f};
            int off;
            off = l - st0;
            if ((unsigned)(off + 3) <= 1026u) {
                #pragma unroll
                for (int j = 0; j < 4; j++) { int o = off + j; if ((unsigned)o < 1024u) { a[j] += cf0 * g_pat[0][o]; c[j] += cf0 * g_pat[1][o]; } }
            }
            off = l - st1;
            if ((unsigned)(off + 3) <= 1026u) {
                #pragma unroll
                for (int j = 0; j < 4; j++) { int o = off + j; if ((unsigned)o < 1024u) { a[j] += cf1 * g_pat[0][o]; c[j] += cf1 * g_pat[1][o]; } }
            }
            off = l - st2;
            if ((unsigned)(off + 3) <= 1026u) {
                #pragma unroll
                for (int j = 0; j < 4; j++) { int o = off + j; if ((unsigned)o < 1024u) { a[j] += cf2 * g_pat[0][o]; c[j] += cf2 * g_pat[1][o]; } }
            }
            off = l - st3;
            if ((unsigned)(off + 3) <= 1026u) {
                #pragma unroll
                for (int j = 0; j < 4; j++) { int o = off + j; if ((unsigned)o < 1024u) { a[j] += cf3 * g_pat[0][o]; c[j] += cf3 * g_pat[1][o]; } }
            }
            float4 oa, ob;
            oa.x = xa.x + a[0]; oa.y = xa.y + a[1]; oa.z = xa.z + a[2]; oa.w = xa.w + a[3];
            ob.x = xb.x + c[0]; ob.y = xb.y + c[1]; ob.z = xb.z + c[2]; ob.w = xb.w + c[3];
            o4[v] = oa;
            o4[1024 + v] = ob;
        }
    }
}

extern "C" void kernel_launch(void* const* d_in, const int* in_sizes, int n_in,
                              void* d_out, int out_size) {
    const float* x          = (const float*)d_in[0];
    const float* pattern_i  = (const float*)d_in[1];
    const float* pattern_q  = (const float*)d_in[2];
    const float* seg_scale  = (const float*)d_in[3];
    const int*   rand_cols  = (const int*)d_in[4];
    const int*   shifts_raw = (const int*)d_in[5];
    float*       out        = (float*)d_out;

    k_init<<<4, 512>>>(pattern_i, pattern_q);
    k_main<<<BATCH, 512>>>(x, seg_scale, rand_cols, shifts_raw, out);
}